// round 4
// baseline (speedup 1.0000x reference)
#include <cuda_runtime.h>
#include <cstdint>
#include <cstddef>

#define NB 32
#define NT 2048
#define ND 512
#define NROWS (NB*NT)   // 65536

// ---------------- scratch (static device arrays; no allocation) ----------------
__device__ float g_xn [(size_t)NROWS*ND];
__device__ float g_nh [(size_t)NROWS*ND];
__device__ float g_ifb[(size_t)NROWS*ND];
__device__ float g_hf [(size_t)NROWS*ND];
__device__ float g_h0 [(size_t)NROWS*ND];
__device__ float g_h1 [(size_t)NROWS*ND];

// ---------------- rmsnorm ----------------
__global__ __launch_bounds__(256) void rmsnorm_kernel(
    const float* __restrict__ x, const float* __restrict__ gamma,
    float* __restrict__ xn)
{
    int row = blockIdx.x * 8 + (threadIdx.x >> 5);
    int l = threadIdx.x & 31;
    const float4* xr = (const float4*)(x + (size_t)row * ND);
    const float4* gp = (const float4*)gamma;
    float4 v[4];
    float ss = 0.f;
#pragma unroll
    for (int i = 0; i < 4; i++) {
        v[i] = xr[l + 32*i];
        ss += v[i].x*v[i].x + v[i].y*v[i].y + v[i].z*v[i].z + v[i].w*v[i].w;
    }
#pragma unroll
    for (int o = 16; o > 0; o >>= 1) ss += __shfl_xor_sync(0xffffffffu, ss, o);
    float n = fmaxf(sqrtf(ss), 1e-12f);
    float s = 22.627416997969522f / n;
    float4* orow = (float4*)(xn + (size_t)row * ND);
#pragma unroll
    for (int i = 0; i < 4; i++) {
        float4 g4 = gp[l + 32*i];
        float4 o;
        o.x = v[i].x * s * (g4.x + 1.f);
        o.y = v[i].y * s * (g4.y + 1.f);
        o.z = v[i].z * s * (g4.z + 1.f);
        o.w = v[i].w * s * (g4.w + 1.f);
        orow[l + 32*i] = o;
    }
}

// ---------------- packed-f32x2 SGEMM: C[M,512] = A[M,512] @ W[512,512] ----------------
// BM=BN=128, BK=16, 256 threads, 8x8 microtile; inner product uses fma.rn.f32x2
// (SASS FFMA2: 2 fp32 MACs per instruction) with column-paired b64 accumulators.
#define SMS 132   // smem row stride in floats (16B-aligned, conflict-free)

template<int ACT>
__global__ __launch_bounds__(256, 2) void sgemm2_kernel(
    const float* __restrict__ A, const float* __restrict__ W,
    float* __restrict__ C)
{
    __shared__ float As[2][16][SMS];
    __shared__ float Bs[2][16][SMS];
    const int tid  = threadIdx.x;
    const int aRow = tid >> 1;          // 0..127
    const int aCol = (tid & 1) * 8;     // 0 or 8
    const int bRow = tid >> 4;          // 0..15
    const int bCol = (tid & 15) * 8;    // 0..120
    const int tr = tid >> 4;            // 0..15 (row group)
    const int tc = tid & 15;            // 0..15 (col group)

    const float* Ap = A + ((size_t)blockIdx.x * 128 + aRow) * ND + aCol;
    const float* Wp = W + (size_t)bRow * ND + blockIdx.y * 128 + bCol;

    unsigned long long acc[8][4];
#pragma unroll
    for (int i = 0; i < 8; i++)
#pragma unroll
        for (int jp = 0; jp < 4; jp++) acc[i][jp] = 0ull;

    // preload stage 0
    float4 pa0 = *(const float4*)(Ap);
    float4 pa1 = *(const float4*)(Ap + 4);
    float4 pb0 = *(const float4*)(Wp);
    float4 pb1 = *(const float4*)(Wp + 4);
    {
        As[0][aCol+0][aRow] = pa0.x; As[0][aCol+1][aRow] = pa0.y;
        As[0][aCol+2][aRow] = pa0.z; As[0][aCol+3][aRow] = pa0.w;
        As[0][aCol+4][aRow] = pa1.x; As[0][aCol+5][aRow] = pa1.y;
        As[0][aCol+6][aRow] = pa1.z; As[0][aCol+7][aRow] = pa1.w;
        *(float4*)&Bs[0][bRow][bCol]     = pb0;
        *(float4*)&Bs[0][bRow][bCol + 4] = pb1;
    }
    __syncthreads();

    const uint32_t asb = (uint32_t)__cvta_generic_to_shared(&As[0][0][0]);
    const uint32_t bsb = (uint32_t)__cvta_generic_to_shared(&Bs[0][0][0]);
    const uint32_t stageBytes = 16u * SMS * 4u;

    for (int s = 0; s < 32; s++) {
        const int cur = s & 1;
        if (s < 31) {
            const int k0 = (s + 1) * 16;
            pa0 = *(const float4*)(Ap + k0);
            pa1 = *(const float4*)(Ap + k0 + 4);
            pb0 = *(const float4*)(Wp + (size_t)k0 * ND);
            pb1 = *(const float4*)(Wp + (size_t)k0 * ND + 4);
        }
        const uint32_t abase = asb + cur * stageBytes + (uint32_t)(tr * 8) * 4u;
        const uint32_t bbase = bsb + cur * stageBytes + (uint32_t)(tc * 8) * 4u;
#pragma unroll
        for (int kk = 0; kk < 16; kk++) {
            float ra[8];
            unsigned long long rb[4];
            asm volatile("ld.shared.v4.f32 {%0,%1,%2,%3},[%4];"
                : "=f"(ra[0]), "=f"(ra[1]), "=f"(ra[2]), "=f"(ra[3])
                : "r"(abase + kk * (SMS*4)));
            asm volatile("ld.shared.v4.f32 {%0,%1,%2,%3},[%4];"
                : "=f"(ra[4]), "=f"(ra[5]), "=f"(ra[6]), "=f"(ra[7])
                : "r"(abase + kk * (SMS*4) + 16));
            asm volatile("ld.shared.v2.u64 {%0,%1},[%2];"
                : "=l"(rb[0]), "=l"(rb[1]) : "r"(bbase + kk * (SMS*4)));
            asm volatile("ld.shared.v2.u64 {%0,%1},[%2];"
                : "=l"(rb[2]), "=l"(rb[3]) : "r"(bbase + kk * (SMS*4) + 16));
#pragma unroll
            for (int i = 0; i < 8; i++) {
                unsigned long long rr;
                asm("mov.b64 %0,{%1,%1};" : "=l"(rr) : "f"(ra[i]));
#pragma unroll
                for (int jp = 0; jp < 4; jp++)
                    asm volatile("fma.rn.f32x2 %0, %1, %2, %0;"
                                 : "+l"(acc[i][jp]) : "l"(rr), "l"(rb[jp]));
            }
        }
        if (s < 31) {
            const int nxt = cur ^ 1;
            As[nxt][aCol+0][aRow] = pa0.x; As[nxt][aCol+1][aRow] = pa0.y;
            As[nxt][aCol+2][aRow] = pa0.z; As[nxt][aCol+3][aRow] = pa0.w;
            As[nxt][aCol+4][aRow] = pa1.x; As[nxt][aCol+5][aRow] = pa1.y;
            As[nxt][aCol+6][aRow] = pa1.z; As[nxt][aCol+7][aRow] = pa1.w;
            *(float4*)&Bs[nxt][bRow][bCol]     = pb0;
            *(float4*)&Bs[nxt][bRow][bCol + 4] = pb1;
        }
        __syncthreads();
    }

    // epilogue
    float* Cp = C + ((size_t)blockIdx.x * 128 + tr * 8) * ND + blockIdx.y * 128 + tc * 8;
#pragma unroll
    for (int i = 0; i < 8; i++) {
        float vv[8];
#pragma unroll
        for (int jp = 0; jp < 4; jp++) {
            float lo, hi;
            asm("mov.b64 {%0,%1},%2;" : "=f"(lo), "=f"(hi) : "l"(acc[i][jp]));
            if (ACT == 1) { lo = tanhf(lo); hi = tanhf(hi); }
            vv[jp*2] = lo; vv[jp*2+1] = hi;
        }
        *(float4*)(Cp + (size_t)i * ND)     = make_float4(vv[0], vv[1], vv[2], vv[3]);
        *(float4*)(Cp + (size_t)i * ND + 4) = make_float4(vv[4], vv[5], vv[6], vv[7]);
    }
}

// ---------------- sequential LRU scan (unchanged from R2) ----------------
__global__ __launch_bounds__(512, 1) void scan_kernel(
    const float* __restrict__ nh, const float* __restrict__ ifg,
    const float* __restrict__ Whf, const float* __restrict__ bhf,
    float* __restrict__ hout)
{
    extern __shared__ float smem[];
    const int rank  = blockIdx.x & 3;
    const int batch = blockIdx.x >> 2;
    const int tid = threadIdx.x;
    const int sub = tid & 3;
    const int jl  = tid >> 2;
    const int j   = rank * 128 + jl;

    const uint32_t sbase = (uint32_t)__cvta_generic_to_shared(smem);
    const uint32_t hb    = sbase + 131072u;

    unsigned long long Wreg[16][2];
#pragma unroll
    for (int c = 0; c < 16; c++) {
        int chunk = (c + 2 * sub) & 31;
        const float* p = Whf + (size_t)(sub * 128 + chunk * 4) * ND + j;
        float w0 = p[0], w1 = p[ND], w2 = p[2 * ND], w3 = p[3 * ND];
        asm("mov.b64 %0,{%1,%2};" : "=l"(Wreg[c][0]) : "f"(w0), "f"(w1));
        asm("mov.b64 %0,{%1,%2};" : "=l"(Wreg[c][1]) : "f"(w2), "f"(w3));
    }
#pragma unroll
    for (int c = 16; c < 32; c++) {
        int chunk = (c + 2 * sub) & 31;
        const float* p = Whf + (size_t)(sub * 128 + chunk * 4) * ND + j;
        float4 v = make_float4(p[0], p[ND], p[2 * ND], p[3 * ND]);
        *(float4*)((char*)smem + tid * 256 + (((c - 16) + tid) & 15) * 16) = v;
    }
    float* hbuf = (float*)((char*)smem + 131072);
    hbuf[tid] = 0.f;
    hbuf[tid + 512] = 0.f;

    float bj = 0.f, h_prev = 0.f;
    const float *nhp = nullptr, *ifp = nullptr;
    float* hop = nullptr;
    uint32_t raddr[2][4];
    if (sub == 0) {
        bj = bhf[j];
        size_t off = (size_t)batch * NT * ND + j;
        nhp = nh + off; ifp = ifg + off; hop = hout + off;
#pragma unroll
        for (int buf = 0; buf < 2; buf++) {
            uint32_t la = hb + (uint32_t)((buf * 512 + j) * 4);
#pragma unroll
            for (int rr = 0; rr < 4; rr++)
                asm("mapa.shared::cluster.u32 %0, %1, %2;"
                    : "=r"(raddr[buf][rr]) : "r"(la), "r"(rr));
        }
    }

    asm volatile("barrier.cluster.arrive.aligned;" ::: "memory");
    asm volatile("barrier.cluster.wait.aligned;"   ::: "memory");

    float nh_cur = 0.f, if_cur = 0.f;
    if (sub == 0) { nh_cur = nhp[0]; if_cur = ifp[0]; }

    for (int t = 0; t < NT; t++) {
        const uint32_t hcur = hb + ((uint32_t)(t & 1) << 11);
        float nh_nxt = 0.f, if_nxt = 0.f;
        if (sub == 0 && t + 1 < NT) {
            nh_nxt = nhp[(size_t)(t + 1) * ND];
            if_nxt = ifp[(size_t)(t + 1) * ND];
        }
        unsigned long long acc0 = 0ull, acc1 = 0ull;
#pragma unroll
        for (int c = 0; c < 16; c++) {
            uint32_t ha = hcur + (uint32_t)((sub * 128 + ((c + 2 * sub) & 31) * 4) * 4);
            unsigned long long h01, h23;
            asm volatile("ld.shared.v2.b64 {%0,%1},[%2];" : "=l"(h01), "=l"(h23) : "r"(ha));
            asm volatile("fma.rn.f32x2 %0, %1, %2, %0;" : "+l"(acc0) : "l"(h01), "l"(Wreg[c][0]));
            asm volatile("fma.rn.f32x2 %0, %1, %2, %0;" : "+l"(acc1) : "l"(h23), "l"(Wreg[c][1]));
        }
#pragma unroll
        for (int c = 16; c < 32; c++) {
            uint32_t ha = hcur + (uint32_t)((sub * 128 + ((c + 2 * sub) & 31) * 4) * 4);
            uint32_t wa = sbase + (uint32_t)(tid * 256 + (((c - 16) + tid) & 15) * 16);
            unsigned long long h01, h23, w01, w23;
            asm volatile("ld.shared.v2.b64 {%0,%1},[%2];" : "=l"(h01), "=l"(h23) : "r"(ha));
            asm volatile("ld.shared.v2.b64 {%0,%1},[%2];" : "=l"(w01), "=l"(w23) : "r"(wa));
            asm volatile("fma.rn.f32x2 %0, %1, %2, %0;" : "+l"(acc0) : "l"(h01), "l"(w01));
            asm volatile("fma.rn.f32x2 %0, %1, %2, %0;" : "+l"(acc1) : "l"(h23), "l"(w23));
        }
        float a0l, a0h, a1l, a1h;
        asm("mov.b64 {%0,%1},%2;" : "=f"(a0l), "=f"(a0h) : "l"(acc0));
        asm("mov.b64 {%0,%1},%2;" : "=f"(a1l), "=f"(a1h) : "l"(acc1));
        float a = (a0l + a0h) + (a1l + a1h);
        a += __shfl_xor_sync(0xffffffffu, a, 1);
        a += __shfl_xor_sync(0xffffffffu, a, 2);
        if (sub == 0) {
            float z = a + bj + if_cur;
            float g = 1.f / (1.f + __expf(-z));
            float hn = fmaf(g, nh_cur - h_prev, h_prev);
            hop[(size_t)t * ND] = hn;
            h_prev = hn;
            const int nb = (t + 1) & 1;
            asm volatile("st.shared::cluster.f32 [%0], %1;" :: "r"(raddr[nb][0]), "f"(hn) : "memory");
            asm volatile("st.shared::cluster.f32 [%0], %1;" :: "r"(raddr[nb][1]), "f"(hn) : "memory");
            asm volatile("st.shared::cluster.f32 [%0], %1;" :: "r"(raddr[nb][2]), "f"(hn) : "memory");
            asm volatile("st.shared::cluster.f32 [%0], %1;" :: "r"(raddr[nb][3]), "f"(hn) : "memory");
        }
        nh_cur = nh_nxt; if_cur = if_nxt;
        asm volatile("barrier.cluster.arrive.aligned;" ::: "memory");
        asm volatile("barrier.cluster.wait.aligned;"   ::: "memory");
    }
}

// ---------------- gate cell combine + residual ----------------
__global__ __launch_bounds__(256) void combine_kernel(
    const float4* __restrict__ x,  const float4* __restrict__ xn,
    const float4* __restrict__ nh, const float4* __restrict__ ifb,
    const float4* __restrict__ hf, const float4* __restrict__ bhf,
    float4* __restrict__ out)
{
    size_t idx = (size_t)blockIdx.x * 256 + threadIdx.x;
    float4 xv = x[idx], xnv = xn[idx], nhv = nh[idx], iv = ifb[idx], hv = hf[idx];
    float4 bv = bhf[idx & 127];
    float4 o;
    { float z = hv.x + bv.x + iv.x; float g = 1.f/(1.f+__expf(-z)); o.x = xv.x + xnv.x + g*(nhv.x - xnv.x); }
    { float z = hv.y + bv.y + iv.y; float g = 1.f/(1.f+__expf(-z)); o.y = xv.y + xnv.y + g*(nhv.y - xnv.y); }
    { float z = hv.z + bv.z + iv.z; float g = 1.f/(1.f+__expf(-z)); o.z = xv.z + xnv.z + g*(nhv.z - xnv.z); }
    { float z = hv.w + bv.w + iv.w; float g = 1.f/(1.f+__expf(-z)); o.w = xv.w + xnv.w + g*(nhv.w - xnv.w); }
    out[idx] = o;
}

// ---------------- launch ----------------
static void launch_scan(const float* nh, const float* ifb,
                        const float* W, const float* b, float* ho)
{
    constexpr int SMEMB = 512*256 + 2*512*4;
    cudaFuncSetAttribute(scan_kernel, cudaFuncAttributeMaxDynamicSharedMemorySize, SMEMB);
    cudaLaunchConfig_t cfg = {};
    cfg.gridDim  = dim3(128, 1, 1);
    cfg.blockDim = dim3(512, 1, 1);
    cfg.dynamicSmemBytes = SMEMB;
    cfg.stream = 0;
    cudaLaunchAttribute attr;
    attr.id = cudaLaunchAttributeClusterDimension;
    attr.val.clusterDim.x = 4; attr.val.clusterDim.y = 1; attr.val.clusterDim.z = 1;
    cfg.attrs = &attr;
    cfg.numAttrs = 1;
    cudaLaunchKernelEx(&cfg, scan_kernel, nh, ifb, W, b, ho);
}

extern "C" void kernel_launch(void* const* d_in, const int* in_sizes, int n_in,
                              void* d_out, int out_size)
{
    const float* x     = (const float*)d_in[0];
    const float* gamma = (const float*)d_in[1];
    const float* gWn   = (const float*)d_in[2];
    const float* gWif  = (const float*)d_in[3];
    const float* gWhf  = (const float*)d_in[4];
    const float* gbhf  = (const float*)d_in[5];
    const float* l0Wn  = (const float*)d_in[6];
    const float* l0Wif = (const float*)d_in[7];
    const float* l0Whf = (const float*)d_in[8];
    const float* l0bhf = (const float*)d_in[9];
    const float* l1Wn  = (const float*)d_in[10];
    const float* l1Wif = (const float*)d_in[11];
    const float* l1Whf = (const float*)d_in[12];
    const float* l1bhf = (const float*)d_in[13];
    float* out = (float*)d_out;

    float *xn, *nh, *ifb, *hf, *h0, *h1;
    cudaGetSymbolAddress((void**)&xn,  g_xn);
    cudaGetSymbolAddress((void**)&nh,  g_nh);
    cudaGetSymbolAddress((void**)&ifb, g_ifb);
    cudaGetSymbolAddress((void**)&hf,  g_hf);
    cudaGetSymbolAddress((void**)&h0,  g_h0);
    cudaGetSymbolAddress((void**)&h1,  g_h1);

    dim3 gg(NROWS / 128, ND / 128);

    rmsnorm_kernel<<<NROWS / 8, 256>>>(x, gamma, xn);

    sgemm2_kernel<1><<<gg, 256>>>(xn, l0Wn,  nh);
    sgemm2_kernel<0><<<gg, 256>>>(xn, l0Wif, ifb);
    launch_scan(nh, ifb, l0Whf, l0bhf, h0);

    sgemm2_kernel<1><<<gg, 256>>>(h0, l1Wn,  nh);
    sgemm2_kernel<0><<<gg, 256>>>(h0, l1Wif, ifb);
    launch_scan(nh, ifb, l1Whf, l1bhf, h1);

    sgemm2_kernel<1><<<gg, 256>>>(h1, gWn,  nh);
    sgemm2_kernel<0><<<gg, 256>>>(h1, gWif, ifb);
    sgemm2_kernel<0><<<gg, 256>>>(xn, gWhf, hf);

    combine_kernel<<<(NROWS * (ND/4)) / 256, 256>>>(
        (const float4*)x, (const float4*)xn, (const float4*)nh,
        (const float4*)ifb, (const float4*)hf, (const float4*)gbhf,
        (float4*)out);
}